// round 7
// baseline (speedup 1.0000x reference)
#include <cuda_runtime.h>

// PoseLSTM v6: v5 mapping + 2 batch elements per thread -> single wave.
//   128 blocks x 800 threads; thread = (l, u, e, gp), handles elems e and e+4
//   2 gate rows (i,f | g,o) per element; weights shared across both elements
//   20x fma.rn.f32x2 per element on k-packed z pairs from LDS.128
//   pair exchange: 2 shfl.xor(1) + 2 sel per element
//   z[buf][layer][elem(8)][24] double buffer; 1 syncthreads per step

#define T_ 1024
#define B_ 1024
#define L_ 10
#define H_ 10
#define NB 8
#define NTH 800

typedef unsigned long long u64;

__device__ __forceinline__ u64 pk2(float lo, float hi) {
    u64 r; asm("mov.b64 %0, {%1,%2};" : "=l"(r) : "f"(lo), "f"(hi)); return r;
}
__device__ __forceinline__ void upk2(u64 v, float& lo, float& hi) {
    asm("mov.b64 {%0,%1}, %2;" : "=f"(lo), "=f"(hi) : "l"(v));
}
__device__ __forceinline__ u64 fma2(u64 a, u64 b, u64 c) {
    u64 d; asm("fma.rn.f32x2 %0, %1, %2, %3;" : "=l"(d) : "l"(a), "l"(b), "l"(c));
    return d;
}
__device__ __forceinline__ u64 add2(u64 a, u64 b) {
    u64 d; asm("add.rn.f32x2 %0, %1, %2;" : "=l"(d) : "l"(a), "l"(b));
    return d;
}
__device__ __forceinline__ float tanhap(float x) {
    float r; asm("tanh.approx.f32 %0, %1;" : "=f"(r) : "f"(x)); return r;
}

__global__ __launch_bounds__(NTH, 1)
void lstm_pipe6(const float* __restrict__ x,   // (T,B,H)
                const float* __restrict__ hp,  // (L,B,H)
                const float* __restrict__ cp,  // (L,B,H)
                const float* __restrict__ Wih, // (L,4H,H)
                const float* __restrict__ Whh, // (L,4H,H)
                const float* __restrict__ bih, // (L,4H)
                const float* __restrict__ bhh, // (L,4H)
                float* __restrict__ out)       // ys ++ hn ++ cn
{
    // z[buf][layer][elem][24]: slots 0..9 input-from-below, 10..19 own h.
    __shared__ __align__(16) float z[2][L_ + 1][NB][24];   // 16896 B

    const int tid = threadIdx.x;
    const int l  = tid / 80;
    const int r  = tid % 80;           // u*8 + e*2 + gp
    const int u  = r >> 3;
    const int e  = (r >> 1) & 3;       // first element slot; second is e+4
    const int gp = r & 1;              // 0: gates (i,f)   1: gates (g~,o)
    const int e2 = e + 4;
    const int b  = blockIdx.x * NB + e;
    const int b2 = b + 4;

    // ---- k-packed register-stationary weights, sigmoid 0.5 folded ----
    const int rowA = l * 40 + gp * 20 + u;    // i (gp0) or g~ (gp1)
    const int rowB = rowA + 10;               // f (gp0) or o  (gp1)
    const float sclA = gp ? 1.0f : 0.5f;
    u64 wA[10], wB[10];
    {
        const float* WiA = Wih + rowA * 10; const float* WhA = Whh + rowA * 10;
        const float* WiB = Wih + rowB * 10; const float* WhB = Whh + rowB * 10;
#pragma unroll
        for (int k = 0; k < 5; ++k) {
            wA[k]     = pk2(sclA * __ldg(WiA + 2 * k), sclA * __ldg(WiA + 2 * k + 1));
            wA[5 + k] = pk2(sclA * __ldg(WhA + 2 * k), sclA * __ldg(WhA + 2 * k + 1));
            wB[k]     = pk2(0.5f * __ldg(WiB + 2 * k), 0.5f * __ldg(WiB + 2 * k + 1));
            wB[5 + k] = pk2(0.5f * __ldg(WhB + 2 * k), 0.5f * __ldg(WhB + 2 * k + 1));
        }
    }
    const float biasA = sclA * (bih[rowA] + bhh[rowA]);
    const float biasB = 0.5f * (bih[rowB] + bhh[rowB]);
    const float cAa = gp ? 0.0f : 0.5f;   // act A: gp0 sigmoid, gp1 tanh
    const float cBa = gp ? 1.0f : 0.5f;

    // ---- init state ----
    float c  = cp[(l * B_ + b ) * H_ + u];
    float c2 = cp[(l * B_ + b2) * H_ + u];
    if (gp == 0) {
        z[l & 1][l][e ][10 + u] = hp[(l * B_ + b ) * H_ + u];
        z[l & 1][l][e2][10 + u] = hp[(l * B_ + b2) * H_ + u];
    }
    const bool isLdr = (l == 0 && gp == 0);
    if (isLdr) {
        z[0][0][e ][u] = x[(size_t)b  * H_ + u];
        z[0][0][e2][u] = x[(size_t)b2 * H_ + u];
    }

    const size_t base_hn = (size_t)T_ * B_ * H_;
    const size_t base_cn = base_hn + (size_t)L_ * B_ * H_;

    // ---- wavefront main loop, parity-unrolled ----
    for (int s0 = 0; s0 < 1034; s0 += 2) {
#pragma unroll
        for (int par = 0; par < 2; ++par) {
            const int scur = s0 + par;
            const int t = scur - l;
            const bool act = ((unsigned)t < (unsigned)T_);

            float xl, xl2;
            const bool ldrGo = isLdr && (scur + 1 < T_);
            if (ldrGo) {
                xl  = x[((size_t)(scur + 1) * B_ + b ) * H_ + u];
                xl2 = x[((size_t)(scur + 1) * B_ + b2) * H_ + u];
            }

            __syncthreads();   // step s-1 z-writes -> step s z-reads

            // ---- matvec: both elements interleaved, 8 indep f32x2 chains ----
            const ulonglong2* zzA =
                reinterpret_cast<const ulonglong2*>(&z[par][l][e ][0]);
            const ulonglong2* zzB =
                reinterpret_cast<const ulonglong2*>(&z[par][l][e2][0]);
            u64 aA  = pk2(biasA, 0.0f), aA_ = pk2(0.0f, 0.0f);
            u64 aB  = pk2(biasB, 0.0f), aB_ = pk2(0.0f, 0.0f);
            u64 bA  = pk2(biasA, 0.0f), bA_ = pk2(0.0f, 0.0f);
            u64 bB  = pk2(biasB, 0.0f), bB_ = pk2(0.0f, 0.0f);
#pragma unroll
            for (int m = 0; m < 5; ++m) {
                ulonglong2 v  = zzA[m];
                ulonglong2 w  = zzB[m];
                aA  = fma2(wA[2 * m],     v.x, aA);
                aA_ = fma2(wA[2 * m + 1], v.y, aA_);
                aB  = fma2(wB[2 * m],     v.x, aB);
                aB_ = fma2(wB[2 * m + 1], v.y, aB_);
                bA  = fma2(wA[2 * m],     w.x, bA);
                bA_ = fma2(wA[2 * m + 1], w.y, bA_);
                bB  = fma2(wB[2 * m],     w.x, bB);
                bB_ = fma2(wB[2 * m + 1], w.y, bB_);
            }
            float pA, pAh, pB, pBh, qA, qAh, qB, qBh;
            { u64 s = add2(aA, aA_); upk2(s, pA, pAh); }
            { u64 s = add2(aB, aB_); upk2(s, pB, pBh); }
            { u64 s = add2(bA, bA_); upk2(s, qA, qAh); }
            { u64 s = add2(bB, bB_); upk2(s, qB, qBh); }
            pA += pAh; pB += pBh; qA += qAh; qB += qBh;

            // ---- activations ----
            float vA  = fmaf(cBa,  tanhap(pA), cAa);
            float vB  = fmaf(0.5f, tanhap(pB), 0.5f);
            float vA2 = fmaf(cBa,  tanhap(qA), cAa);
            float vB2 = fmaf(0.5f, tanhap(qB), 0.5f);

            // ---- pair exchange + cell update (both elements) ----
            float Ao  = __shfl_xor_sync(0xFFFFFFFFu, vA, 1);
            float Bo  = __shfl_xor_sync(0xFFFFFFFFu, vB, 1);
            float Ao2 = __shfl_xor_sync(0xFFFFFFFFu, vA2, 1);
            float Bo2 = __shfl_xor_sync(0xFFFFFFFFu, vB2, 1);
            float F  = gp ? Bo  : vB;
            float O  = gp ? vB  : Bo;
            float F2 = gp ? Bo2 : vB2;
            float O2 = gp ? vB2 : Bo2;
            if (act) {
                c  = fmaf(F,  c,  vA  * Ao);
                c2 = fmaf(F2, c2, vA2 * Ao2);
            }
            float h  = O  * tanhap(c);
            float h2 = O2 * tanhap(c2);

            // ---- h handoff / outputs ----
            if (act) {
                if (gp == 0) {
                    z[par ^ 1][l][e ][10 + u] = h;
                    z[par ^ 1][l][e2][10 + u] = h2;
                } else if (l < L_ - 1) {
                    z[par ^ 1][l + 1][e ][u] = h;
                    z[par ^ 1][l + 1][e2][u] = h2;
                } else {
                    out[((size_t)t * B_ + b ) * H_ + u] = h;
                    out[((size_t)t * B_ + b2) * H_ + u] = h2;
                }
                if (t == T_ - 1) {
                    if (gp == 0) {
                        out[base_hn + ((size_t)l * B_ + b ) * H_ + u] = h;
                        out[base_hn + ((size_t)l * B_ + b2) * H_ + u] = h2;
                    } else {
                        out[base_cn + ((size_t)l * B_ + b ) * H_ + u] = c;
                        out[base_cn + ((size_t)l * B_ + b2) * H_ + u] = c2;
                    }
                }
            }
            if (ldrGo) {
                z[par ^ 1][0][e ][u] = xl;
                z[par ^ 1][0][e2][u] = xl2;
            }
        }
    }
}

extern "C" void kernel_launch(void* const* d_in, const int* in_sizes, int n_in,
                              void* d_out, int out_size) {
    const float* x   = (const float*)d_in[0];
    const float* hp  = (const float*)d_in[1];
    const float* cp  = (const float*)d_in[2];
    const float* Wih = (const float*)d_in[3];
    const float* Whh = (const float*)d_in[4];
    const float* bih = (const float*)d_in[5];
    const float* bhh = (const float*)d_in[6];
    float* out = (float*)d_out;

    dim3 grid(B_ / NB);   // 128 blocks -> single wave on 148 SMs
    dim3 block(NTH);      // 800 threads = 25 full warps
    lstm_pipe6<<<grid, block>>>(x, hp, cp, Wih, Whh, bih, bhh, out);
}